// round 16
// baseline (speedup 1.0000x reference)
#include <cuda_runtime.h>
#include <cstdint>
#include <cstddef>

#define BB 64
#define TT 512
#define EE 300
#define HH 1024
#define GG 3072   // 3*HH
#define OO 5

#define NB 128    // blocks in persistent recurrent kernel (1 per SM)
#define JPB 8     // HH / NB hidden units per block
#define THR 1024  // 32 warps = 16 k-segments x 2 b-halves

// ---------------- device scratch ----------------
__device__ float g_gx[(size_t)TT * GG * BB];   // [t][g][b]
__device__ float g_WT[EE * GG];                // W_ih transposed: [e][g]
__device__ float g_h[4][HH * BB];              // hidden 4-deep ring, [j][b]
__device__ unsigned g_flags[NB * 32];          // flag[p*32] = completed steps + 1

// ---------------- f32x2 helpers (sm_103a packed fp32) ----------------
__device__ __forceinline__ void fma2(uint64_t& a, uint64_t b, uint64_t c) {
    asm("fma.rn.f32x2 %0, %1, %2, %0;" : "+l"(a) : "l"(b), "l"(c));
}
__device__ __forceinline__ uint64_t dup2(float x) {
    uint64_t r; asm("mov.b64 %0, {%1, %1};" : "=l"(r) : "f"(x)); return r;
}
__device__ __forceinline__ void unpk(uint64_t v, float& lo, float& hi) {
    asm("mov.b64 {%0, %1}, %2;" : "=f"(lo), "=f"(hi) : "l"(v));
}
__device__ __forceinline__ unsigned ldacq(const unsigned* p) {
    unsigned v;
    asm volatile("ld.global.acquire.gpu.u32 %0, [%1];" : "=r"(v) : "l"(p) : "memory");
    return v;
}
__device__ __forceinline__ void strel(unsigned* p, unsigned v) {
    asm volatile("st.global.release.gpu.u32 [%0], %1;" :: "l"(p), "r"(v) : "memory");
}

// ---------------- tiny helpers ----------------
__global__ void k_reset() { if (threadIdx.x < NB) g_flags[threadIdx.x * 32] = 0u; }

__global__ void k_transpose(const float* __restrict__ Wih) {
    int i = blockIdx.x * blockDim.x + threadIdx.x;
    if (i < EE * GG) {
        int e = i / GG, g = i - e * GG;
        g_WT[i] = Wih[(size_t)g * EE + e];
    }
}

// ---------------- kernel A: gx[t][g][b] (FFMA2) ----------------
__global__ void __launch_bounds__(256) k_gx(const int* __restrict__ x,
                                            const float* __restrict__ emb,
                                            const float* __restrict__ bih) {
    extern __shared__ float sm[];
    float* embS = sm;            // [e][b]
    float* Wt   = sm + EE * BB;  // [e][64] current g-tile

    const int t   = blockIdx.x;
    const int tid = threadIdx.x;

    for (int i = tid; i < BB * EE; i += 256) {
        int b = i / EE, e = i - b * EE;
        embS[e * BB + b] = emb[(size_t)x[b * TT + t] * EE + e];
    }

    const int bg = tid & 31;
    const int gy = tid >> 5;

    for (int gt = 0; gt < GG / 64; gt++) {
        __syncthreads();
        for (int i = tid; i < EE * 64; i += 256) {
            int e = i >> 6, g = i & 63;
            Wt[i] = g_WT[e * GG + gt * 64 + g];
        }
        __syncthreads();

        uint64_t a0[4], a1[4];
        uint64_t z0 = dup2(0.f);
#pragma unroll
        for (int p = 0; p < 4; p++) { a0[p] = z0; a1[p] = z0; }

#pragma unroll 4
        for (int e = 0; e < EE; e++) {
            float2 eb = *(float2*)&embS[e * BB + bg * 2];
            uint64_t e0 = dup2(eb.x), e1 = dup2(eb.y);
            ulonglong2 wv0 = *(const ulonglong2*)&Wt[e * 64 + gy * 8];
            ulonglong2 wv1 = *(const ulonglong2*)&Wt[e * 64 + gy * 8 + 4];
            fma2(a0[0], wv0.x, e0); fma2(a1[0], wv0.x, e1);
            fma2(a0[1], wv0.y, e0); fma2(a1[1], wv0.y, e1);
            fma2(a0[2], wv1.x, e0); fma2(a1[2], wv1.x, e1);
            fma2(a0[3], wv1.y, e0); fma2(a1[3], wv1.y, e1);
        }
#pragma unroll
        for (int p = 0; p < 4; p++) {
            int j = gt * 64 + gy * 8 + 2 * p;
            float l0, h0, l1, h1;
            unpk(a0[p], l0, h0);
            unpk(a1[p], l1, h1);
            float bj = bih[j], bk = bih[j + 1];
            size_t base = ((size_t)t * GG + j) * BB + bg * 2;
            g_gx[base]          = l0 + bj;
            g_gx[base + 1]      = l1 + bj;
            g_gx[base + BB]     = h0 + bk;
            g_gx[base + BB + 1] = h1 + bk;
        }
    }
}

__device__ __forceinline__ float sigf(float v) { return 1.0f / (1.0f + expf(-v)); }

// ---------------- kernel B: persistent GRU recurrence, 32 warps ----------------
// Warp w: kseg = w>>1 owns k in [64*kseg, 64*kseg+64); bhalf = w&1 owns 32 b's.
// Lane: bg = lane&7 (4 b's), jg = lane>>3 (j-pair). 12 packed acc/lane.
// part tile per (kseg, gate): [4 jg][64 b] u64 -> disjoint slots per producer.
__global__ void __launch_bounds__(THR, 1) k_rnn(const float* __restrict__ Whh,
                                                const float* __restrict__ bhh) {
    extern __shared__ float sm[];
    float* Wsm     = sm;                      // [3][1024][8] = 24576 floats (96 KB)
    uint64_t* part = (uint64_t*)(sm + 24576); // [16][3][4][64] u64 = 12288 (96 KB)

    const int tid  = threadIdx.x;
    const int w    = tid >> 5, lane = tid & 31;
    const int kseg = w >> 1;
    const int bh   = (w & 1) * 32;
    const int bg   = lane & 7, jg = lane >> 3;
    const int jbase = blockIdx.x * JPB;

    // load W_hh slice once: Wsm[(g*1024+k)*8 + jl]
    for (int i = tid; i < 3 * HH * JPB; i += THR) {
        int jl = i & 7, k = (i >> 3) & (HH - 1), g = i >> 13;
        Wsm[i] = Whh[((size_t)(g * HH + jbase + jl)) * HH + k];
    }

    // consumer role (tid < 512): one (j, b) per thread
    const int cj  = tid >> 6;           // 0..7
    const int cb  = tid & 63;
    const int jglob = jbase + cj;
    const float br = bhh[jglob], bz = bhh[HH + jglob], bn = bhh[2 * HH + jglob];
    const bool consumer = (tid < 512);
    // float offset inside one [s][g] tile ([4 jg][64 b] u64 = 512 floats):
    const int cfl = ((cj >> 1) * 64 + cb) * 2 + (cj & 1);

    // zero own slice of h_0 (ring slot 0), publish flag = 1
    for (int i = tid; i < JPB * BB; i += THR)
        __stcg(&g_h[0][jbase * BB + i], 0.f);
    __threadfence();
    __syncthreads();
    if (tid == 0) strel(&g_flags[blockIdx.x * 32], 1u);

    const uint64_t zz = dup2(0.f);
    const int kb = kseg * 64;
    const unsigned* pflag = &g_flags[(8 * kseg + (lane & 7)) * 32];

    for (int t = 0; t < TT; t++) {
        const float* hin  = g_h[t & 3];
        float*       hout = g_h[(t + 1) & 3];

        // gate-operand prefetch (consumers; own slice / static gx)
        float xr, xz, xn, hp;
        if (consumer) {
            const float* gxt = g_gx + (size_t)t * GG * BB;
            xr = __ldcg(&gxt[(0 * HH + jglob) * BB + cb]);
            xz = __ldcg(&gxt[(1 * HH + jglob) * BB + cb]);
            xn = __ldcg(&gxt[(2 * HH + jglob) * BB + cb]);
            hp = __ldcg(&hin[jglob * BB + cb]);
        }

        // wait for the 8 producers of this warp's k-range
        if (lane < 8) {
            while (ldacq(pflag) < (unsigned)(t + 1)) { }
        }
        __syncwarp();

        uint64_t aR[4], aZ[4], aN[4];
#pragma unroll
        for (int b = 0; b < 4; b++) { aR[b] = zz; aZ[b] = zz; aN[b] = zz; }

        // ---- k-loop: h from L2 (coalescer dedups jg replication), W from smem ----
        const float* hk = hin + (size_t)kb * BB + bh + bg * 4;
#pragma unroll 8
        for (int k2 = 0; k2 < 64; k2++) {
            const int k = kb + k2;
            float4 ha = __ldcg((const float4*)(hk + k2 * BB));
            uint64_t wr  = *(const uint64_t*)&Wsm[(0 * HH + k) * 8 + jg * 2];
            uint64_t wz2 = *(const uint64_t*)&Wsm[(1 * HH + k) * 8 + jg * 2];
            uint64_t wn2 = *(const uint64_t*)&Wsm[(2 * HH + k) * 8 + jg * 2];
            uint64_t d0 = dup2(ha.x), d1 = dup2(ha.y), d2 = dup2(ha.z), d3 = dup2(ha.w);
            fma2(aR[0], wr, d0);  fma2(aR[1], wr, d1);  fma2(aR[2], wr, d2);  fma2(aR[3], wr, d3);
            fma2(aZ[0], wz2, d0); fma2(aZ[1], wz2, d1); fma2(aZ[2], wz2, d2); fma2(aZ[3], wz2, d3);
            fma2(aN[0], wn2, d0); fma2(aN[1], wn2, d1); fma2(aN[2], wn2, d2); fma2(aN[3], wn2, d3);
        }

        // ---- store partials: part[kseg][g][jg][bh + bg*4 + bi] (disjoint) ----
        {
            const int bb = bh + bg * 4;
#pragma unroll
            for (int bi = 0; bi < 4; bi++) {
                part[((kseg * 3 + 0) * 4 + jg) * 64 + bb + bi] = aR[bi];
                part[((kseg * 3 + 1) * 4 + jg) * 64 + bb + bi] = aZ[bi];
                part[((kseg * 3 + 2) * 4 + jg) * 64 + bb + bi] = aN[bi];
            }
        }

        // writer gate: h_{t+1} overwrites h_{t-3}; steady-state no-op
        if (t >= 3 && tid < NB) {
            const unsigned* fp = &g_flags[tid * 32];
            while (ldacq(fp) < (unsigned)(t - 1)) { }
        }
        __syncthreads();

        // ---- consume: 16-way reduction + gates ----
        if (consumer) {
            const float* pf = (const float*)part;
            float sR = 0.f, sZ = 0.f, sN = 0.f;
#pragma unroll
            for (int s = 0; s < 16; s++) {
                sR += pf[(s * 3 + 0) * 512 + cfl];
                sZ += pf[(s * 3 + 1) * 512 + cfl];
                sN += pf[(s * 3 + 2) * 512 + cfl];
            }
            float r = sigf(xr + sR + br);
            float z = sigf(xz + sZ + bz);
            float n = tanhf(xn + r * (sN + bn));
            __stcg(&hout[jglob * BB + cb], (1.f - z) * n + z * hp);
        }

        __threadfence();
        __syncthreads();   // h stores done + part reads done before next step
        if (tid == 0) strel(&g_flags[blockIdx.x * 32], (unsigned)(t + 2));
    }
}

// ---------------- kernel C: FC ----------------
__global__ void k_fc(const float* __restrict__ Wfc, const float* __restrict__ bfc,
                     float* __restrict__ out) {
    int tid = threadIdx.x;
    if (tid >= BB * OO) return;
    int b = tid & 63, o = tid >> 6;
    const float* h = g_h[0];   // h_512 in ring slot 512 & 3 = 0
    float a0 = 0.f, a1 = 0.f, a2 = 0.f, a3 = 0.f;
    for (int j = 0; j < HH; j += 4) {
        a0 += h[(j + 0) * BB + b] * Wfc[o * HH + j + 0];
        a1 += h[(j + 1) * BB + b] * Wfc[o * HH + j + 1];
        a2 += h[(j + 2) * BB + b] * Wfc[o * HH + j + 2];
        a3 += h[(j + 3) * BB + b] * Wfc[o * HH + j + 3];
    }
    out[b * OO + o] = a0 + a1 + a2 + a3 + bfc[o];
}

// ---------------- entry ----------------
extern "C" void kernel_launch(void* const* d_in, const int* in_sizes, int n_in,
                              void* d_out, int out_size) {
    const int*   x   = (const int*)d_in[0];
    const float* emb = (const float*)d_in[1];
    const float* Wih = (const float*)d_in[2];
    const float* Whh = (const float*)d_in[3];
    const float* bih = (const float*)d_in[4];
    const float* bhh = (const float*)d_in[5];
    const float* Wfc = (const float*)d_in[6];
    const float* bfc = (const float*)d_in[7];
    float* out = (float*)d_out;

    const int smemA = 2 * EE * BB * (int)sizeof(float);          // 153.6 KB
    const int smemB = (24576 + 24576) * (int)sizeof(float);      // 192 KB
    cudaFuncSetAttribute(k_gx,  cudaFuncAttributeMaxDynamicSharedMemorySize, smemA);
    cudaFuncSetAttribute(k_rnn, cudaFuncAttributeMaxDynamicSharedMemorySize, smemB);

    k_reset<<<1, 128>>>();
    k_transpose<<<(EE * GG + 255) / 256, 256>>>(Wih);
    k_gx<<<TT, 256, smemA>>>(x, emb, bih);
    k_rnn<<<NB, THR, smemB>>>(Whh, bhh);
    k_fc<<<1, 512>>>(Wfc, bfc, out);
}

// round 17
// speedup vs baseline: 1.2366x; 1.2366x over previous
#include <cuda_runtime.h>
#include <cstdint>
#include <cstddef>

#define BB 64
#define TT 512
#define EE 300
#define HH 1024
#define GG 3072   // 3*HH
#define OO 5

#define NB 128    // blocks in persistent recurrent kernel (1 per SM)
#define JPB 8     // HH / NB hidden units per block
#define THR 576   // 16 GEMM warps + 2 consumer warps

// ---------------- device scratch ----------------
__device__ float g_gx[(size_t)TT * GG * BB];   // [t][g][b]
__device__ float g_WT[EE * GG];                // W_ih transposed: [e][g]
__device__ float g_h[4][HH * BB];              // hidden 4-deep ring, [j][b]
__device__ unsigned g_flags[NB * 32];          // flag[p*32] = completed steps + 1

// ---------------- f32x2 helpers (sm_103a packed fp32) ----------------
__device__ __forceinline__ void fma2(uint64_t& a, uint64_t b, uint64_t c) {
    asm("fma.rn.f32x2 %0, %1, %2, %0;" : "+l"(a) : "l"(b), "l"(c));
}
__device__ __forceinline__ uint64_t dup2(float x) {
    uint64_t r; asm("mov.b64 %0, {%1, %1};" : "=l"(r) : "f"(x)); return r;
}
__device__ __forceinline__ void unpk(uint64_t v, float& lo, float& hi) {
    asm("mov.b64 {%0, %1}, %2;" : "=f"(lo), "=f"(hi) : "l"(v));
}
__device__ __forceinline__ unsigned ldacq(const unsigned* p) {
    unsigned v;
    asm volatile("ld.global.acquire.gpu.u32 %0, [%1];" : "=r"(v) : "l"(p) : "memory");
    return v;
}
__device__ __forceinline__ void strel(unsigned* p, unsigned v) {
    asm volatile("st.global.release.gpu.u32 [%0], %1;" :: "l"(p), "r"(v) : "memory");
}
#define BAR_SYNC(id, cnt)   asm volatile("bar.sync %0, %1;"   :: "r"(id), "r"(cnt) : "memory")
#define BAR_ARRIVE(id, cnt) asm volatile("bar.arrive %0, %1;" :: "r"(id), "r"(cnt) : "memory")
#define MEMBAR_CTA()        asm volatile("membar.cta;" ::: "memory")

// ---------------- tiny helpers ----------------
__global__ void k_reset() { if (threadIdx.x < NB) g_flags[threadIdx.x * 32] = 0u; }

__global__ void k_transpose(const float* __restrict__ Wih) {
    int i = blockIdx.x * blockDim.x + threadIdx.x;
    if (i < EE * GG) {
        int e = i / GG, g = i - e * GG;
        g_WT[i] = Wih[(size_t)g * EE + e];
    }
}

// ---------------- kernel A: gx[t][g][b] (FFMA2, unchanged from best) ----------------
__global__ void __launch_bounds__(256) k_gx(const int* __restrict__ x,
                                            const float* __restrict__ emb,
                                            const float* __restrict__ bih) {
    extern __shared__ float sm[];
    float* embS = sm;            // [e][b]
    float* Wt   = sm + EE * BB;  // [e][64] current g-tile

    const int t   = blockIdx.x;
    const int tid = threadIdx.x;

    for (int i = tid; i < BB * EE; i += 256) {
        int b = i / EE, e = i - b * EE;
        embS[e * BB + b] = emb[(size_t)x[b * TT + t] * EE + e];
    }

    const int bg = tid & 31;
    const int gy = tid >> 5;

    for (int gt = 0; gt < GG / 64; gt++) {
        __syncthreads();
        for (int i = tid; i < EE * 64; i += 256) {
            int e = i >> 6, g = i & 63;
            Wt[i] = g_WT[e * GG + gt * 64 + g];
        }
        __syncthreads();

        uint64_t a0[4], a1[4];
        uint64_t z0 = dup2(0.f);
#pragma unroll
        for (int p = 0; p < 4; p++) { a0[p] = z0; a1[p] = z0; }

#pragma unroll 4
        for (int e = 0; e < EE; e++) {
            float2 eb = *(float2*)&embS[e * BB + bg * 2];
            uint64_t e0 = dup2(eb.x), e1 = dup2(eb.y);
            ulonglong2 wv0 = *(const ulonglong2*)&Wt[e * 64 + gy * 8];
            ulonglong2 wv1 = *(const ulonglong2*)&Wt[e * 64 + gy * 8 + 4];
            fma2(a0[0], wv0.x, e0); fma2(a1[0], wv0.x, e1);
            fma2(a0[1], wv0.y, e0); fma2(a1[1], wv0.y, e1);
            fma2(a0[2], wv1.x, e0); fma2(a1[2], wv1.x, e1);
            fma2(a0[3], wv1.y, e0); fma2(a1[3], wv1.y, e1);
        }
#pragma unroll
        for (int p = 0; p < 4; p++) {
            int j = gt * 64 + gy * 8 + 2 * p;
            float l0, h0, l1, h1;
            unpk(a0[p], l0, h0);
            unpk(a1[p], l1, h1);
            float bj = bih[j], bk = bih[j + 1];
            size_t base = ((size_t)t * GG + j) * BB + bg * 2;
            g_gx[base]          = l0 + bj;
            g_gx[base + 1]      = l1 + bj;
            g_gx[base + BB]     = h0 + bk;
            g_gx[base + BB + 1] = h1 + bk;
        }
    }
}

__device__ __forceinline__ float sigf(float v) { return 1.0f / (1.0f + expf(-v)); }

// ---------------- kernel B: persistent GRU recurrence, role-split ----------------
// Warps 0..15: GEMM producers (kseg = wid), identical R8 k-loop.
// Warps 16,17: consumers (reduction + gates + h publish), overlapped with the
// producers' NEXT-step GEMM via named barriers:
//   bar 1 "partials ready": producers arrive, consumers sync.
//   bar 2 "buffer free":    consumers arrive (right after reads), producers sync.
//   bar 3: consumer-pair internal sync before flag publish (cnt=64).
__global__ void __launch_bounds__(THR, 1) k_rnn(const float* __restrict__ Whh,
                                                const float* __restrict__ bhh) {
    extern __shared__ float sm[];
    float* Wsm     = sm;                      // [3][1024][8] = 24576 floats (96 KB)
    uint64_t* part = (uint64_t*)(sm + 24576); // [16][3][4][32] u64 = 12288 (96 KB)

    const int tid  = threadIdx.x;
    const int w    = tid >> 5, lane = tid & 31;
    const int jbase = blockIdx.x * JPB;

    // load W_hh slice once: Wsm[(g*1024+k)*8 + jl]
    for (int i = tid; i < 3 * HH * JPB; i += THR) {
        int jl = i & 7, k = (i >> 3) & (HH - 1), g = i >> 13;
        Wsm[i] = Whh[((size_t)(g * HH + jbase + jl)) * HH + k];
    }

    // zero own slice of h_0 (ring slot 0), publish flag = 1
    for (int i = tid; i < JPB * BB; i += THR)
        __stcg(&g_h[0][jbase * BB + i], 0.f);
    __threadfence();
    __syncthreads();
    if (tid == 0) strel(&g_flags[blockIdx.x * 32], 1u);

    if (w < 16) {
        // ================= GEMM producer =================
        const int bg = lane & 7, jg = lane >> 3;
        const int kb = w * 64;
        const unsigned* pflag = &g_flags[(8 * w + (lane & 7)) * 32];
        const uint64_t zz = dup2(0.f);

        for (int t = 0; t < TT; t++) {
            const float* hin = g_h[t & 3];

            // wait for the 8 producers of this warp's k-range to publish h_t
            if (lane < 8) {
                while (ldacq(pflag) < (unsigned)(t + 1)) { }
            }
            __syncwarp();

            uint64_t aR[8], aZ[8], aN[8];
#pragma unroll
            for (int b = 0; b < 8; b++) { aR[b] = zz; aZ[b] = zz; aN[b] = zz; }

            const float* hk = hin + (size_t)kb * BB + bg * 8;
#pragma unroll 4
            for (int k2 = 0; k2 < 64; k2++) {
                const int k = kb + k2;
                float4 ha = __ldcg((const float4*)(hk + k2 * BB));
                float4 hc = __ldcg((const float4*)(hk + k2 * BB + 4));
                uint64_t wr  = *(const uint64_t*)&Wsm[(0 * HH + k) * 8 + jg * 2];
                uint64_t wz2 = *(const uint64_t*)&Wsm[(1 * HH + k) * 8 + jg * 2];
                uint64_t wn2 = *(const uint64_t*)&Wsm[(2 * HH + k) * 8 + jg * 2];
                uint64_t d0 = dup2(ha.x), d1 = dup2(ha.y), d2 = dup2(ha.z), d3 = dup2(ha.w);
                uint64_t d4 = dup2(hc.x), d5 = dup2(hc.y), d6 = dup2(hc.z), d7 = dup2(hc.w);
                fma2(aR[0], wr, d0);  fma2(aR[1], wr, d1);  fma2(aR[2], wr, d2);  fma2(aR[3], wr, d3);
                fma2(aR[4], wr, d4);  fma2(aR[5], wr, d5);  fma2(aR[6], wr, d6);  fma2(aR[7], wr, d7);
                fma2(aZ[0], wz2, d0); fma2(aZ[1], wz2, d1); fma2(aZ[2], wz2, d2); fma2(aZ[3], wz2, d3);
                fma2(aZ[4], wz2, d4); fma2(aZ[5], wz2, d5); fma2(aZ[6], wz2, d6); fma2(aZ[7], wz2, d7);
                fma2(aN[0], wn2, d0); fma2(aN[1], wn2, d1); fma2(aN[2], wn2, d2); fma2(aN[3], wn2, d3);
                fma2(aN[4], wn2, d4); fma2(aN[5], wn2, d5); fma2(aN[6], wn2, d6); fma2(aN[7], wn2, d7);
            }

            // buffer must be free (consumer read previous step's partials)
            BAR_SYNC(2, THR);
#pragma unroll
            for (int bi = 0; bi < 8; bi++) {
                int col = ((jg * 8 + bg) + bi * 8) & 31;   // R8 swizzle
                part[(w * 3 + 0) * 256 + bi * 32 + col] = aR[bi];
                part[(w * 3 + 1) * 256 + bi * 32 + col] = aZ[bi];
                part[(w * 3 + 2) * 256 + bi * 32 + col] = aN[bi];
            }
            MEMBAR_CTA();
            BAR_ARRIVE(1, THR);   // partials ready; proceed to next step immediately
        }
    } else {
        // ================= consumer =================
        const int cl  = tid - 512;          // 0..63
        const int cj  = cl >> 3;            // 0..7
        const int cbq = cl & 7;             // b-octet
        const int b0  = cbq * 8;
        const int jglob = jbase + cj;
        const int cjg = cj >> 1, cpar = cj & 1;
        const float br = bhh[jglob], bz = bhh[HH + jglob], bn = bhh[2 * HH + jglob];

        float hp[8];
#pragma unroll
        for (int i = 0; i < 8; i++) hp[i] = 0.f;   // h_0 = 0 (carried in regs)

        BAR_ARRIVE(2, THR);   // prime: buffer initially free

        for (int t = 0; t < TT; t++) {
            float* hout = g_h[(t + 1) & 3];

            // prefetch this thread's gx operands (static, no cross-block dep)
            const float* gxt = g_gx + (size_t)t * GG * BB;
            float4 xra = __ldcg((const float4*)&gxt[(0 * HH + jglob) * BB + b0]);
            float4 xrb = __ldcg((const float4*)&gxt[(0 * HH + jglob) * BB + b0 + 4]);
            float4 xza = __ldcg((const float4*)&gxt[(1 * HH + jglob) * BB + b0]);
            float4 xzb = __ldcg((const float4*)&gxt[(1 * HH + jglob) * BB + b0 + 4]);
            float4 xna = __ldcg((const float4*)&gxt[(2 * HH + jglob) * BB + b0]);
            float4 xnb = __ldcg((const float4*)&gxt[(2 * HH + jglob) * BB + b0 + 4]);
            float xr[8] = {xra.x, xra.y, xra.z, xra.w, xrb.x, xrb.y, xrb.z, xrb.w};
            float xz[8] = {xza.x, xza.y, xza.z, xza.w, xzb.x, xzb.y, xzb.z, xzb.w};
            float xn[8] = {xna.x, xna.y, xna.z, xna.w, xnb.x, xnb.y, xnb.z, xnb.w};

            // writer gate: h_{t+1} overwrites h_{t-3}; need all blocks past t-3.
            if (t >= 3) {
                while (ldacq(&g_flags[cl * 32]) < (unsigned)(t - 1)) { }
                while (ldacq(&g_flags[(cl + 64) * 32]) < (unsigned)(t - 1)) { }
            }

            BAR_SYNC(1, THR);   // partials ready

            const float* pf = (const float*)part;
            float hnew[8];
#pragma unroll
            for (int i = 0; i < 8; i++) {
                int col = ((cjg * 8 + cbq) + i * 8) & 31;
                int fl  = (i * 32 + col) * 2 + cpar;
                float sR = 0.f, sZ = 0.f, sN = 0.f;
#pragma unroll
                for (int s = 0; s < 16; s++) {
                    sR += pf[s * 1536 + 0 * 512 + fl];
                    sZ += pf[s * 1536 + 1 * 512 + fl];
                    sN += pf[s * 1536 + 2 * 512 + fl];
                }
                float r = sigf(xr[i] + sR + br);
                float z = sigf(xz[i] + sZ + bz);
                float n = tanhf(xn[i] + r * (sN + bn));
                hnew[i] = (1.f - z) * n + z * hp[i];
                hp[i] = hnew[i];
            }
            BAR_ARRIVE(2, THR);   // reads consumed into regs -> buffer free

            float4 o0, o1;
            o0.x = hnew[0]; o0.y = hnew[1]; o0.z = hnew[2]; o0.w = hnew[3];
            o1.x = hnew[4]; o1.y = hnew[5]; o1.z = hnew[6]; o1.w = hnew[7];
            __stcg((float4*)&hout[jglob * BB + b0], o0);
            __stcg((float4*)&hout[jglob * BB + b0 + 4], o1);

            __threadfence();
            BAR_SYNC(3, 64);      // both consumer warps' h stores fenced
            if (cl == 0) strel(&g_flags[blockIdx.x * 32], (unsigned)(t + 2));
        }
    }
}

// ---------------- kernel C: FC ----------------
__global__ void k_fc(const float* __restrict__ Wfc, const float* __restrict__ bfc,
                     float* __restrict__ out) {
    int tid = threadIdx.x;
    if (tid >= BB * OO) return;
    int b = tid & 63, o = tid >> 6;
    const float* h = g_h[0];   // h_512 in ring slot 512 & 3 = 0
    float a0 = 0.f, a1 = 0.f, a2 = 0.f, a3 = 0.f;
    for (int j = 0; j < HH; j += 4) {
        a0 += h[(j + 0) * BB + b] * Wfc[o * HH + j + 0];
        a1 += h[(j + 1) * BB + b] * Wfc[o * HH + j + 1];
        a2 += h[(j + 2) * BB + b] * Wfc[o * HH + j + 2];
        a3 += h[(j + 3) * BB + b] * Wfc[o * HH + j + 3];
    }
    out[b * OO + o] = a0 + a1 + a2 + a3 + bfc[o];
}

// ---------------- entry ----------------
extern "C" void kernel_launch(void* const* d_in, const int* in_sizes, int n_in,
                              void* d_out, int out_size) {
    const int*   x   = (const int*)d_in[0];
    const float* emb = (const float*)d_in[1];
    const float* Wih = (const float*)d_in[2];
    const float* Whh = (const float*)d_in[3];
    const float* bih = (const float*)d_in[4];
    const float* bhh = (const float*)d_in[5];
    const float* Wfc = (const float*)d_in[6];
    const float* bfc = (const float*)d_in[7];
    float* out = (float*)d_out;

    const int smemA = 2 * EE * BB * (int)sizeof(float);          // 153.6 KB
    const int smemB = (24576 + 24576) * (int)sizeof(float);      // 192 KB
    cudaFuncSetAttribute(k_gx,  cudaFuncAttributeMaxDynamicSharedMemorySize, smemA);
    cudaFuncSetAttribute(k_rnn, cudaFuncAttributeMaxDynamicSharedMemorySize, smemB);

    k_reset<<<1, 128>>>();
    k_transpose<<<(EE * GG + 255) / 256, 256>>>(Wih);
    k_gx<<<TT, 256, smemA>>>(x, emb, bih);
    k_rnn<<<NB, THR, smemB>>>(Whh, bhh);
    k_fc<<<1, 512>>>(Wfc, bfc, out);
}